// round 1
// baseline (speedup 1.0000x reference)
#include <cuda_runtime.h>

#define BB    2
#define CC    64
#define NN    16384
#define KK    16
#define COUT  64
#define RR    128           // rows of combined matrix [A; W2]
#define TN    64            // GEMM node tile

// ---------------- scratch (device globals; no allocation allowed) ----------
__device__ float g_mean[BB][CC];
__device__ float g_cvec[BB][COUT];
__device__ float g_Mt[CC][RR];           // transposed combined matrix [c][r]
__device__ float g_Y[(size_t)BB * NN * RR]; // 16 MB transformed features
__device__ int   g_is64;

// ---------------- dtype detection for edge_index ---------------------------
__global__ void detect_kernel(const void* e) {
    const unsigned long long* p = (const unsigned long long*)e;
    int is64 = 1;
    #pragma unroll
    for (int i = 0; i < 8; i++)
        if (p[i] >= (unsigned long long)NN) is64 = 0;
    g_is64 = is64;
}

// ---------------- mean over nodes: g_mean[b][c] ----------------------------
__global__ __launch_bounds__(256) void mean_kernel(const float* __restrict__ x) {
    int row = blockIdx.x;                 // b*CC + c
    const float4* xr = (const float4*)(x + (size_t)row * NN);
    float s = 0.f;
    for (int i = threadIdx.x; i < NN / 4; i += 256) {
        float4 v = xr[i];
        s += v.x + v.y + v.z + v.w;
    }
    __shared__ float sm[256];
    sm[threadIdx.x] = s;
    __syncthreads();
    for (int st = 128; st > 0; st >>= 1) {
        if (threadIdx.x < st) sm[threadIdx.x] += sm[threadIdx.x + st];
        __syncthreads();
    }
    if (threadIdx.x == 0)
        ((float*)g_mean)[row] = sm[0] * (1.0f / NN);
}

// ---------------- build Mt and cvec ----------------------------------------
__global__ __launch_bounds__(128) void prep_kernel(const float* __restrict__ W,
                                                   const float* __restrict__ bias) {
    int t = threadIdx.x;  // 0..127
    // Mt[c][t]: t<64 -> W1-W2 rows; t>=64 -> W2 rows
    for (int c = 0; c < CC; c++) {
        float v;
        if (t < 64) v = W[t * 192 + c] - W[t * 192 + 64 + c];
        else        v = W[(t - 64) * 192 + 64 + c];
        g_Mt[c][t] = v;
    }
    // cvec[b][o] = bias[o] + W3[o,:] . mean[b,:]
    int b = t >> 6, o = t & 63;
    float s = bias[o];
    for (int c = 0; c < CC; c++)
        s += W[o * 192 + 128 + c] * g_mean[b][c];
    g_cvec[b][o] = s;
}

// ---------------- GEMM: Y[b][n][r] = sum_c Mt[c][r] * x[b][c][n] ------------
__global__ __launch_bounds__(256) void gemm_kernel(const float* __restrict__ x) {
    __shared__ __align__(16) float Ms[CC][RR];   // 32 KB
    __shared__ __align__(16) float Xs[CC][TN];   // 16 KB   (total 48 KB)
    int b  = blockIdx.y;
    int n0 = blockIdx.x * TN;
    int tid = threadIdx.x;

    for (int i = tid; i < CC * RR; i += 256)
        ((float*)Ms)[i] = ((const float*)g_Mt)[i];
    const float* xb = x + (size_t)b * CC * NN;
    for (int i = tid; i < CC * TN; i += 256) {
        int c = i / TN, j = i % TN;
        Xs[c][j] = xb[c * NN + n0 + j];
    }
    __syncthreads();

    int tr = tid & 15;   // r-group: handles r = tr*4..+3 and 64+tr*4..+3
    int tn = tid >> 4;   // n-group: handles n = tn*4..+3
    float acc[4][8];
    #pragma unroll
    for (int a = 0; a < 4; a++)
        #pragma unroll
        for (int r = 0; r < 8; r++) acc[a][r] = 0.f;

    #pragma unroll 4
    for (int c = 0; c < CC; c++) {
        float4 m0 = *(const float4*)&Ms[c][tr * 4];
        float4 m1 = *(const float4*)&Ms[c][64 + tr * 4];
        float4 xv = *(const float4*)&Xs[c][tn * 4];
        float xa[4] = {xv.x, xv.y, xv.z, xv.w};
        float ma[8] = {m0.x, m0.y, m0.z, m0.w, m1.x, m1.y, m1.z, m1.w};
        #pragma unroll
        for (int a = 0; a < 4; a++)
            #pragma unroll
            for (int r = 0; r < 8; r++)
                acc[a][r] = fmaf(xa[a], ma[r], acc[a][r]);
    }

    float* Yb = g_Y + (size_t)b * NN * RR;
    #pragma unroll
    for (int a = 0; a < 4; a++) {
        int n = n0 + tn * 4 + a;
        float4 v0 = make_float4(acc[a][0], acc[a][1], acc[a][2], acc[a][3]);
        float4 v1 = make_float4(acc[a][4], acc[a][5], acc[a][6], acc[a][7]);
        *(float4*)&Yb[(size_t)n * RR + tr * 4]      = v0;
        *(float4*)&Yb[(size_t)n * RR + 64 + tr * 4] = v1;
    }
}

// ---------------- gather + max-relu epilogue --------------------------------
// Block: 256 threads = (64 channels) x (4 node subgroups); 32 nodes per block.
__global__ __launch_bounds__(256) void gather_kernel(const void* __restrict__ eidx,
                                                     float* __restrict__ out) {
    int bn = blockIdx.x;                 // 0..1023
    int b  = bn >> 9;                    // NN/32 = 512 blocks per batch
    int n0 = (bn & 511) * 32;
    int tid = threadIdx.x;
    int tx = tid & 63;                   // channel
    int tg = tid >> 6;                   // node subgroup 0..3

    __shared__ int   s_idx[32][2][KK];   // [local node][i/j][k]
    __shared__ float s_out[COUT][33];    // padded: conflict-free column stores

    int is64 = g_is64;
    const long long* e64 = (const long long*)eidx;
    const int*       e32 = (const int*)eidx;
    for (int i = tid; i < 32 * KK; i += 256) {
        int ln = i / KK, k = i % KK;
        long long bj = ((long long)(0 * BB + b) * NN + (n0 + ln)) * KK + k;
        long long bi = ((long long)(1 * BB + b) * NN + (n0 + ln)) * KK + k;
        int vi, vj;
        if (is64) { vj = (int)e64[bj]; vi = (int)e64[bi]; }
        else      { vj = e32[bj];      vi = e32[bi]; }
        s_idx[ln][0][k] = vi;
        s_idx[ln][1][k] = vj;
    }
    __syncthreads();

    float cv = g_cvec[b][tx];
    const float* Yb = g_Y + (size_t)b * NN * RR;

    #pragma unroll
    for (int it = 0; it < 8; it++) {
        int ln = it * 4 + tg;
        float m = 0.f;                   // relu floor folded into max
        #pragma unroll
        for (int k = 0; k < KK; k++) {
            int i = s_idx[ln][0][k];
            int j = s_idx[ln][1][k];
            float v = Yb[i * RR + tx] + Yb[j * RR + 64 + tx] + cv;
            m = fmaxf(m, v);
        }
        s_out[tx][ln] = m;
    }
    __syncthreads();

    float* ob = out + (size_t)b * COUT * NN;
    for (int i = tid; i < COUT * 32; i += 256) {
        int ch = i >> 5, j = i & 31;
        ob[ch * NN + n0 + j] = s_out[ch][j];
    }
}

// ---------------- launch ----------------------------------------------------
extern "C" void kernel_launch(void* const* d_in, const int* in_sizes, int n_in,
                              void* d_out, int out_size) {
    const float* x    = (const float*)d_in[0];
    const void*  eidx = d_in[1];
    const float* W    = (const float*)d_in[2];
    const float* bias = (const float*)d_in[3];
    float* out = (float*)d_out;

    detect_kernel<<<1, 32>>>(eidx);
    mean_kernel<<<BB * CC, 256>>>(x);
    prep_kernel<<<1, 128>>>(W, bias);
    gemm_kernel<<<dim3(NN / TN, BB), 256>>>(x);
    gather_kernel<<<BB * NN / 32, 256>>>(eidx, out);
}

// round 2
// speedup vs baseline: 1.7637x; 1.7637x over previous
#include <cuda_runtime.h>
#include <cuda_fp16.h>

#define BB    2
#define CC    64
#define NN    16384
#define KK    16
#define COUT  64
#define RR    128           // rows of combined matrix [W1-W2 ; W2]
#define TNB   256           // GEMM nodes per block

// ---------------- scratch (device globals; no allocation allowed) ----------
__device__ float  g_mean[BB][CC];
__device__ float  g_cvec[BB][COUT];
__device__ float  g_Mt[CC][RR];                // transposed combined matrix [c][r]
__device__ __half g_Yh[(size_t)BB * NN * RR];  // 8 MB transformed features (fp16)
__device__ int    g_is64;

// ---------------- f32x2 helpers (sm_103a packed fp32 FMA) -------------------
#define FMA_F32X2(d, a, b) \
    asm("fma.rn.f32x2 %0, %1, %2, %0;" : "+l"(d) : "l"(a), "l"(b))

__device__ __forceinline__ unsigned long long pack2(float lo, float hi) {
    unsigned long long r;
    asm("mov.b64 %0, {%1, %2};" : "=l"(r) : "f"(lo), "f"(hi));
    return r;
}

// ---------------- dtype detection for edge_index ---------------------------
__global__ void detect_kernel(const void* e) {
    const unsigned long long* p = (const unsigned long long*)e;
    int is64 = 1;
    #pragma unroll
    for (int i = 0; i < 8; i++)
        if (p[i] >= (unsigned long long)NN) is64 = 0;
    g_is64 = is64;
}

// ---------------- mean over nodes: g_mean[b][c] ----------------------------
__global__ __launch_bounds__(256) void mean_kernel(const float* __restrict__ x) {
    int row = blockIdx.x;                 // b*CC + c
    const float4* xr = (const float4*)(x + (size_t)row * NN);
    float s = 0.f;
    for (int i = threadIdx.x; i < NN / 4; i += 256) {
        float4 v = xr[i];
        s += v.x + v.y + v.z + v.w;
    }
    __shared__ float sm[256];
    sm[threadIdx.x] = s;
    __syncthreads();
    for (int st = 128; st > 0; st >>= 1) {
        if (threadIdx.x < st) sm[threadIdx.x] += sm[threadIdx.x + st];
        __syncthreads();
    }
    if (threadIdx.x == 0)
        ((float*)g_mean)[row] = sm[0] * (1.0f / NN);
}

// ---------------- build Mt and cvec ----------------------------------------
__global__ __launch_bounds__(128) void prep_kernel(const float* __restrict__ W,
                                                   const float* __restrict__ bias) {
    int t = threadIdx.x;  // 0..127
    for (int c = 0; c < CC; c++) {
        float v;
        if (t < 64) v = W[t * 192 + c] - W[t * 192 + 64 + c];   // W1 - W2
        else        v = W[(t - 64) * 192 + 64 + c];             // W2
        g_Mt[c][t] = v;
    }
    int b = t >> 6, o = t & 63;
    float s = bias[o];
    for (int c = 0; c < CC; c++)
        s += W[o * 192 + 128 + c] * g_mean[b][c];               // W3 . mean
    g_cvec[b][o] = s;
}

// ---------------- GEMM: Yh[b][n][r] = sum_c Mt[c][r] * x[b][c][n] -----------
// 128 blocks total (64 n-tiles x 2 batches). Per-thread tile: 16 n x 8 r,
// accumulators packed as f32x2 over node pairs (x-pairs load natively from smem).
__global__ __launch_bounds__(256, 1) void gemm_kernel(const float* __restrict__ x) {
    __shared__ __align__(16) float Ms[CC][RR];    // 32 KB
    __shared__ __align__(16) float Xs[CC][TNB];   // 64 KB
    int b   = blockIdx.y;
    int n0  = blockIdx.x * TNB;
    int tid = threadIdx.x;

    for (int i = tid; i < CC * RR / 4; i += 256)
        ((float4*)Ms)[i] = ((const float4*)g_Mt)[i];
    const float* xb = x + (size_t)b * CC * NN;
    for (int i = tid; i < CC * TNB / 4; i += 256) {
        int c = i / (TNB / 4), j = i % (TNB / 4);
        ((float4*)&Xs[c][0])[j] = ((const float4*)(xb + (size_t)c * NN + n0))[j];
    }
    __syncthreads();

    int rg = tid & 15;    // r = rg*8 .. rg*8+7
    int ng = tid >> 4;    // n = n0 + ng*16 .. +15  (8 node-pairs)
    unsigned long long acc[8][8];   // [npair][r], each = (f32 lo=n even, hi=n odd)
    #pragma unroll
    for (int p = 0; p < 8; p++)
        #pragma unroll
        for (int r = 0; r < 8; r++) acc[p][r] = 0ull;

    #pragma unroll 2
    for (int c = 0; c < CC; c++) {
        float4 m0 = *(const float4*)&Ms[c][rg * 8];
        float4 m1 = *(const float4*)&Ms[c][rg * 8 + 4];
        unsigned long long mp[8];
        mp[0] = pack2(m0.x, m0.x); mp[1] = pack2(m0.y, m0.y);
        mp[2] = pack2(m0.z, m0.z); mp[3] = pack2(m0.w, m0.w);
        mp[4] = pack2(m1.x, m1.x); mp[5] = pack2(m1.y, m1.y);
        mp[6] = pack2(m1.z, m1.z); mp[7] = pack2(m1.w, m1.w);
        const unsigned long long* xr =
            (const unsigned long long*)&Xs[c][ng * 16];
        unsigned long long xp[8];
        #pragma unroll
        for (int p = 0; p < 8; p++) xp[p] = xr[p];
        #pragma unroll
        for (int p = 0; p < 8; p++)
            #pragma unroll
            for (int r = 0; r < 8; r++)
                FMA_F32X2(acc[p][r], xp[p], mp[r]);
    }

    __half* Yb = g_Yh + (size_t)b * NN * RR;
    #pragma unroll
    for (int p = 0; p < 8; p++) {
        #pragma unroll
        for (int s = 0; s < 2; s++) {
            int n = n0 + ng * 16 + 2 * p + s;
            float v[8];
            #pragma unroll
            for (int r = 0; r < 8; r++) {
                uint2 u = *(uint2*)&acc[p][r];
                v[r] = __uint_as_float(s == 0 ? u.x : u.y);
            }
            __half2 h0 = __floats2half2_rn(v[0], v[1]);
            __half2 h1 = __floats2half2_rn(v[2], v[3]);
            __half2 h2 = __floats2half2_rn(v[4], v[5]);
            __half2 h3 = __floats2half2_rn(v[6], v[7]);
            uint4 pk;
            pk.x = *(unsigned*)&h0; pk.y = *(unsigned*)&h1;
            pk.z = *(unsigned*)&h2; pk.w = *(unsigned*)&h3;
            *(uint4*)(Yb + (size_t)n * RR + rg * 8) = pk;
        }
    }
}

// ---------------- gather + max-relu epilogue --------------------------------
// Block: 256 threads = 8 warps; block handles 64 nodes, warp handles 8 nodes.
// Per (node,k): one half2 load/lane covers all 64 channels of the i-part (128B)
// and one for the j-part. Math in fp32; relu folded into max floor.
__global__ __launch_bounds__(256) void gather_kernel(const void* __restrict__ eidx,
                                                     float* __restrict__ out) {
    int bn   = blockIdx.x;               // 0..511
    int b    = bn >> 8;                  // NN/64 = 256 blocks per batch
    int n0   = (bn & 255) * 64;
    int tid  = threadIdx.x;
    int lane = tid & 31;
    int w    = tid >> 5;

    __shared__ int   s_idx[64][2][KK];   // 8 KB
    __shared__ float s_o[64][65];        // [node][ch], padded: conflict-free reads

    int is64 = g_is64;
    const long long* e64 = (const long long*)eidx;
    const int*       e32 = (const int*)eidx;
    for (int i = tid; i < 64 * KK; i += 256) {
        int ln = i >> 4, k = i & 15;
        size_t bj = ((size_t)(0 * BB + b) * NN + (n0 + ln)) * KK + k;
        size_t bi = ((size_t)(1 * BB + b) * NN + (n0 + ln)) * KK + k;
        int vi, vj;
        if (is64) { vj = (int)e64[bj]; vi = (int)e64[bi]; }
        else      { vj = e32[bj];      vi = e32[bi]; }
        s_idx[ln][0][k] = vi;            // center  (edge_index[1])
        s_idx[ln][1][k] = vj;            // neighbor (edge_index[0])
    }
    __syncthreads();

    float2 cv = ((const float2*)g_cvec[b])[lane];   // channels 2*lane, 2*lane+1
    const __half* Yb = g_Yh + (size_t)b * NN * RR;

    for (int t = 0; t < 8; t++) {
        int ln = w * 8 + t;
        float m0 = 0.f, m1 = 0.f;        // relu floor folded in
        #pragma unroll
        for (int k = 0; k < KK; k++) {
            int i = s_idx[ln][0][k];
            int j = s_idx[ln][1][k];
            __half2 hi = ((const __half2*)(Yb + (size_t)i * RR))[lane];
            __half2 hj = ((const __half2*)(Yb + (size_t)j * RR + 64))[lane];
            float2 fi = __half22float2(hi);
            float2 fj = __half22float2(hj);
            m0 = fmaxf(m0, fi.x + fj.x + cv.x);
            m1 = fmaxf(m1, fi.y + fj.y + cv.y);
        }
        s_o[ln][2 * lane]     = m0;
        s_o[ln][2 * lane + 1] = m1;
    }
    __syncthreads();

    float* ob = out + (size_t)b * COUT * NN;
    for (int i = tid; i < COUT * 64; i += 256) {
        int ch = i >> 6, j = i & 63;
        ob[ch * NN + n0 + j] = s_o[j][ch];
    }
}

// ---------------- launch ----------------------------------------------------
extern "C" void kernel_launch(void* const* d_in, const int* in_sizes, int n_in,
                              void* d_out, int out_size) {
    const float* x    = (const float*)d_in[0];
    const void*  eidx = d_in[1];
    const float* W    = (const float*)d_in[2];
    const float* bias = (const float*)d_in[3];
    float* out = (float*)d_out;

    detect_kernel<<<1, 32>>>(eidx);
    mean_kernel<<<BB * CC, 256>>>(x);
    prep_kernel<<<1, 128>>>(W, bias);
    gemm_kernel<<<dim3(NN / TNB, BB), 256>>>(x);
    gather_kernel<<<BB * NN / 64, 256>>>(eidx, out);
}

// round 3
// speedup vs baseline: 1.7657x; 1.0011x over previous
#include <cuda_runtime.h>
#include <cuda_fp16.h>

#define BB    2
#define CC    64
#define NN    16384
#define KK    16
#define COUT  64
#define RR    128           // rows of combined matrix [W1-W2 ; W2]
#define TNB   128           // GEMM nodes per block

// ---------------- scratch (device globals; no allocation allowed) ----------
__device__ float  g_mean[BB][CC];
__device__ float  g_cvec[BB][COUT];
__device__ float  g_Mt[CC][RR];                // transposed combined matrix [c][r]
__device__ __half g_Yh[(size_t)BB * NN * RR];  // 8 MB transformed features (fp16)
__device__ int    g_is64;

// ---------------- f32x2 helpers (sm_103a packed fp32 FMA) -------------------
#define FMA_F32X2(d, a, b) \
    asm("fma.rn.f32x2 %0, %1, %2, %0;" : "+l"(d) : "l"(a), "l"(b))

__device__ __forceinline__ unsigned long long pack2(float lo, float hi) {
    unsigned long long r;
    asm("mov.b64 %0, {%1, %2};" : "=l"(r) : "f"(lo), "f"(hi));
    return r;
}

// ---------------- dtype detection for edge_index ---------------------------
__global__ void detect_kernel(const void* e) {
    const unsigned long long* p = (const unsigned long long*)e;
    int is64 = 1;
    #pragma unroll
    for (int i = 0; i < 8; i++)
        if (p[i] >= (unsigned long long)NN) is64 = 0;
    g_is64 = is64;
}

// ---------------- mean over nodes: g_mean[b][c] ----------------------------
__global__ __launch_bounds__(256) void mean_kernel(const float* __restrict__ x) {
    int row = blockIdx.x;                 // b*CC + c
    const float4* xr = (const float4*)(x + (size_t)row * NN);
    float s = 0.f;
    for (int i = threadIdx.x; i < NN / 4; i += 256) {
        float4 v = xr[i];
        s += v.x + v.y + v.z + v.w;
    }
    __shared__ float sm[256];
    sm[threadIdx.x] = s;
    __syncthreads();
    for (int st = 128; st > 0; st >>= 1) {
        if (threadIdx.x < st) sm[threadIdx.x] += sm[threadIdx.x + st];
        __syncthreads();
    }
    if (threadIdx.x == 0)
        ((float*)g_mean)[row] = sm[0] * (1.0f / NN);
}

// ---------------- build Mt and cvec ----------------------------------------
__global__ __launch_bounds__(128) void prep_kernel(const float* __restrict__ W,
                                                   const float* __restrict__ bias) {
    int t = threadIdx.x;  // 0..127
    for (int c = 0; c < CC; c++) {
        float v;
        if (t < 64) v = W[t * 192 + c] - W[t * 192 + 64 + c];   // W1 - W2
        else        v = W[(t - 64) * 192 + 64 + c];             // W2
        g_Mt[c][t] = v;
    }
    int b = t >> 6, o = t & 63;
    float s = bias[o];
    for (int c = 0; c < CC; c++)
        s += W[o * 192 + 128 + c] * g_mean[b][c];               // W3 . mean
    g_cvec[b][o] = s;
}

// ---------------- GEMM: Yh[b][n][r] = sum_c Mt[c][r] * x[b][c][n] -----------
// grid (128, 2) = 256 blocks, 2 blocks/SM (64 KB smem, <=128 regs).
// Per-thread tile: 8 n (4 f32x2 pairs) x 8 r.
__global__ __launch_bounds__(256, 2) void gemm_kernel(const float* __restrict__ x) {
    __shared__ __align__(16) float Ms[CC][RR];    // 32 KB
    __shared__ __align__(16) float Xs[CC][TNB];   // 32 KB
    int b   = blockIdx.y;
    int n0  = blockIdx.x * TNB;
    int tid = threadIdx.x;

    for (int i = tid; i < CC * RR / 4; i += 256)
        ((float4*)Ms)[i] = ((const float4*)g_Mt)[i];
    const float* xb = x + (size_t)b * CC * NN;
    for (int i = tid; i < CC * TNB / 4; i += 256) {
        int c = i >> 5, j = i & 31;   // TNB/4 = 32
        ((float4*)&Xs[c][0])[j] = ((const float4*)(xb + (size_t)c * NN + n0))[j];
    }
    __syncthreads();

    int rg = tid & 15;    // r = rg*8 .. +7
    int ng = tid >> 4;    // n = n0 + ng*8 .. +7 (4 node-pairs)
    unsigned long long acc[4][8];   // [npair][r]
    #pragma unroll
    for (int p = 0; p < 4; p++)
        #pragma unroll
        for (int r = 0; r < 8; r++) acc[p][r] = 0ull;

    #pragma unroll 4
    for (int c = 0; c < CC; c++) {
        float4 m0 = *(const float4*)&Ms[c][rg * 8];       // warp-broadcast
        float4 m1 = *(const float4*)&Ms[c][rg * 8 + 4];
        const unsigned long long* xr = (const unsigned long long*)&Xs[c][ng * 8];
        unsigned long long xp[4];
        #pragma unroll
        for (int p = 0; p < 4; p++) xp[p] = xr[p];
        unsigned long long mp[8];
        mp[0] = pack2(m0.x, m0.x); mp[1] = pack2(m0.y, m0.y);
        mp[2] = pack2(m0.z, m0.z); mp[3] = pack2(m0.w, m0.w);
        mp[4] = pack2(m1.x, m1.x); mp[5] = pack2(m1.y, m1.y);
        mp[6] = pack2(m1.z, m1.z); mp[7] = pack2(m1.w, m1.w);
        #pragma unroll
        for (int p = 0; p < 4; p++)
            #pragma unroll
            for (int r = 0; r < 8; r++)
                FMA_F32X2(acc[p][r], xp[p], mp[r]);
    }

    __half* Yb = g_Yh + (size_t)b * NN * RR;
    #pragma unroll
    for (int p = 0; p < 4; p++) {
        #pragma unroll
        for (int s = 0; s < 2; s++) {
            int n = n0 + ng * 8 + 2 * p + s;
            float v[8];
            #pragma unroll
            for (int r = 0; r < 8; r++) {
                uint2 u = *(uint2*)&acc[p][r];
                v[r] = __uint_as_float(s == 0 ? u.x : u.y);
            }
            __half2 h0 = __floats2half2_rn(v[0], v[1]);
            __half2 h1 = __floats2half2_rn(v[2], v[3]);
            __half2 h2 = __floats2half2_rn(v[4], v[5]);
            __half2 h3 = __floats2half2_rn(v[6], v[7]);
            uint4 pk;
            pk.x = *(unsigned*)&h0; pk.y = *(unsigned*)&h1;
            pk.z = *(unsigned*)&h2; pk.w = *(unsigned*)&h3;
            *(uint4*)(Yb + (size_t)n * RR + rg * 8) = pk;
        }
    }
}

// ---------------- gather + max-relu epilogue --------------------------------
// Block 256 thr = 8 warps, 64 nodes/block, warp handles 8 nodes.
// Warp layout: lane = kg*8 + cq; kg in 0..3 covers k = kg*4..+3,
// cq in 0..7 covers channels cq*8..+7 (16B -> one LDG.128 per edge part).
// Butterfly max-reduce over kg at the end.
__global__ __launch_bounds__(256) void gather_kernel(const void* __restrict__ eidx,
                                                     float* __restrict__ out) {
    int bn   = blockIdx.x;               // 0..511
    int b    = bn >> 8;                  // 256 blocks per batch
    int n0   = (bn & 255) * 64;
    int tid  = threadIdx.x;
    int lane = tid & 31;
    int w    = tid >> 5;
    int kg   = lane >> 3;
    int cq   = lane & 7;

    __shared__ int   s_idx[64][2][KK];   // 8 KB
    __shared__ float s_o[64][65];        // padded, conflict-free

    int is64 = g_is64;
    const long long* e64 = (const long long*)eidx;
    const int*       e32 = (const int*)eidx;
    for (int i = tid; i < 64 * KK; i += 256) {
        int ln = i >> 4, k = i & 15;
        size_t bj = ((size_t)(0 * BB + b) * NN + (n0 + ln)) * KK + k;
        size_t bi = ((size_t)(1 * BB + b) * NN + (n0 + ln)) * KK + k;
        int vi, vj;
        if (is64) { vj = (int)e64[bj]; vi = (int)e64[bi]; }
        else      { vj = e32[bj];      vi = e32[bi]; }
        s_idx[ln][0][k] = vi;            // center   (edge_index[1])
        s_idx[ln][1][k] = vj;            // neighbor (edge_index[0])
    }
    __syncthreads();

    // per-lane channel constants (8 channels = 4 float2)
    float2 cv[4];
    #pragma unroll
    for (int t = 0; t < 4; t++)
        cv[t] = ((const float2*)g_cvec[b])[cq * 4 + t];

    const __half* Yb = g_Yh + (size_t)b * NN * RR;

    for (int t = 0; t < 8; t++) {
        int ln = w * 8 + t;
        float2 m[4];
        #pragma unroll
        for (int u = 0; u < 4; u++) m[u] = make_float2(0.f, 0.f);  // relu floor

        #pragma unroll
        for (int kit = 0; kit < 4; kit++) {
            int k = kg * 4 + kit;
            int i = s_idx[ln][0][k];
            int j = s_idx[ln][1][k];
            uint4 vi = *(const uint4*)(Yb + (size_t)i * RR + cq * 8);
            uint4 vj = *(const uint4*)(Yb + (size_t)j * RR + 64 + cq * 8);
            const unsigned* pi = (const unsigned*)&vi;
            const unsigned* pj = (const unsigned*)&vj;
            #pragma unroll
            for (int u = 0; u < 4; u++) {
                float2 fi = __half22float2(*(const __half2*)&pi[u]);
                float2 fj = __half22float2(*(const __half2*)&pj[u]);
                m[u].x = fmaxf(m[u].x, fi.x + fj.x + cv[u].x);
                m[u].y = fmaxf(m[u].y, fi.y + fj.y + cv[u].y);
            }
        }

        // max-reduce across k-groups (lanes xor 8, then xor 16)
        #pragma unroll
        for (int off = 8; off <= 16; off <<= 1) {
            #pragma unroll
            for (int u = 0; u < 4; u++) {
                m[u].x = fmaxf(m[u].x, __shfl_xor_sync(0xFFFFFFFFu, m[u].x, off));
                m[u].y = fmaxf(m[u].y, __shfl_xor_sync(0xFFFFFFFFu, m[u].y, off));
            }
        }
        if (kg == 0) {
            #pragma unroll
            for (int u = 0; u < 4; u++) {
                s_o[ln][cq * 8 + 2 * u]     = m[u].x;
                s_o[ln][cq * 8 + 2 * u + 1] = m[u].y;
            }
        }
    }
    __syncthreads();

    float* ob = out + (size_t)b * COUT * NN;
    for (int i = tid; i < COUT * 64; i += 256) {
        int ch = i >> 6, j = i & 63;
        ob[ch * NN + n0 + j] = s_o[j][ch];
    }
}

// ---------------- launch ----------------------------------------------------
extern "C" void kernel_launch(void* const* d_in, const int* in_sizes, int n_in,
                              void* d_out, int out_size) {
    const float* x    = (const float*)d_in[0];
    const void*  eidx = d_in[1];
    const float* W    = (const float*)d_in[2];
    const float* bias = (const float*)d_in[3];
    float* out = (float*)d_out;

    detect_kernel<<<1, 32>>>(eidx);
    mean_kernel<<<BB * CC, 256>>>(x);
    prep_kernel<<<1, 128>>>(W, bias);
    gemm_kernel<<<dim3(NN / TNB, BB), 256>>>(x);
    gather_kernel<<<BB * NN / 64, 256>>>(eidx, out);
}